// round 14
// baseline (speedup 1.0000x reference)
#include <cuda_runtime.h>
#include <cuda_bf16.h>
#include <stdint.h>

typedef unsigned long long ull;

#define Bn  16
#define ICn 3
#define QCn 8
#define VCn 16
#define Hn  224
#define Wn  224
#define H2  112

// ---- scratch: device globals (no runtime allocation allowed) ----
__device__ float g_q [Bn*24*H2*H2];          // [b][i*8+qc][112][112]
__device__ float g_v [Bn*16*H2*H2];          // [b][vc][112][112]
__device__ float g_S [1152*784];             // [(b,i,qc,c)][pq*49+uv]
__device__ float g_Qs[Bn*ICn*QCn*16];        // [(b,i,qc)][pq]
__device__ float g_a [Bn*ICn*VCn*16];        // [(b,i)][vc*16+pq]
// Pre-shifted bf16 operands, rows padded to 128 elems (256 B):
//  g_qsh[qp][mat][(b,i,qc)][y][j] = hi/lo( q_pad[y][j+2qp] )
//  g_xsh[v ][mat][(b,c)  ][y][j] = hi/lo( x_pad[y][2j+v] )
__device__ __align__(16) __nv_bfloat16 g_qsh[4*2*384*112*128];
__device__ __align__(16) __nv_bfloat16 g_xsh[7*2*48*224*128];

#define QSH_MATSTRIDE 11010048   // 384*112*256 bytes
#define QSH_QCSTRIDE  28672      // 112*256
#define XSH_MATSTRIDE 2752512    // 48*224*256 bytes
#define XSH_BCSTRIDE  57344      // 224*256

#define FMA2(d,a,b) asm("fma.rn.f32x2 %0, %1, %2, %0;" : "+l"(d) : "l"(a), "l"(b))
#define DUP2(d,s)   asm("mov.b64 %0, {%1, %1};" : "=l"(d) : "f"(s))

__device__ __forceinline__ uint32_t smem_to_u32(const void* p) {
    uint32_t a;
    asm("{ .reg .u64 t; cvta.to.shared.u64 t, %1; cvt.u32.u64 %0, t; }" : "=r"(a) : "l"(p));
    return a;
}

#define LDSM_X4(r0,r1,r2,r3,addr) \
    asm volatile("ldmatrix.sync.aligned.m8n8.x4.shared.b16 {%0,%1,%2,%3}, [%4];" \
        : "=r"(r0),"=r"(r1),"=r"(r2),"=r"(r3) : "r"(addr))

#define MMA16816(d,a,b0,b1) \
    asm volatile("mma.sync.aligned.m16n8k16.row.col.f32.bf16.bf16.f32 " \
        "{%0,%1,%2,%3}, {%4,%5,%6,%7}, {%8,%9}, {%0,%1,%2,%3};" \
        : "+f"((d)[0]),"+f"((d)[1]),"+f"((d)[2]),"+f"((d)[3]) \
        : "r"((a)[0]),"r"((a)[1]),"r"((a)[2]),"r"((a)[3]), "r"(b0),"r"(b1))

#define CP_ASYNC16(dst, src, sz) \
    asm volatile("cp.async.cg.shared.global [%0], [%1], 16, %2;" \
        :: "r"(dst), "l"(src), "r"(sz) : "memory")
#define CP_COMMIT()  asm volatile("cp.async.commit_group;" ::: "memory")
#define CP_WAIT1()   asm volatile("cp.async.wait_group 1;" ::: "memory")
#define CP_WAIT0()   asm volatile("cp.async.wait_group 0;" ::: "memory")

// ===========================================================================
// Kernel A: fused static convs q (24 ch) + v (16 ch), stride 2, pad 3.
// ===========================================================================
__global__ __launch_bounds__(224) void k_convqv(
    const float* __restrict__ x,
    const float* __restrict__ Wq, const float* __restrict__ bq,
    const float* __restrict__ Wv, const float* __restrict__ bv)
{
    __shared__ __align__(16) float xs[3*7*232];
    __shared__ __align__(16) float ws[147*40];
    __shared__ __align__(16) float bs[40];
    const int oy = blockIdx.x, b = blockIdx.y;
    const int tid = threadIdx.x;

    for (int t = tid; t < 24*147; t += 224) { int oc=t/147, cuv=t%147; ws[cuv*40+oc]    = Wq[t]; }
    for (int t = tid; t < 16*147; t += 224) { int oc=t/147, cuv=t%147; ws[cuv*40+24+oc] = Wv[t]; }
    if (tid < 24) bs[tid] = bq[tid];
    else if (tid < 40) bs[tid] = bv[tid-24];

    const float* xb = x + b*ICn*Hn*Wn;
    for (int t = tid; t < 3*7*232; t += 224) {
        int cc = t/(7*232), r = (t/232)%7, j = t%232;
        int row = 2*oy - 3 + r, col = j - 3;
        float v = 0.f;
        if (row >= 0 && row < Hn && col >= 0 && col < Wn) v = xb[(cc*Hn+row)*Wn + col];
        xs[t] = v;
    }
    __syncthreads();

    const int half = tid/112, ox = tid%112;
    ull acc2[10];
    {
        const float2* b2 = reinterpret_cast<const float2*>(bs + half*20);
        #pragma unroll
        for (int k = 0; k < 10; k++) {
            float2 t = b2[k];
            asm("mov.b64 %0, {%1, %2};" : "=l"(acc2[k]) : "f"(t.x), "f"(t.y));
        }
    }
    #pragma unroll 1
    for (int cc = 0; cc < 3; cc++)
      #pragma unroll 1
      for (int u = 0; u < 7; u++) {
        const float* xr = &xs[(cc*7+u)*232 + 2*ox];
        const ull*  wr = reinterpret_cast<const ull*>(&ws[(cc*49+u*7)*40 + half*20]);
        #pragma unroll
        for (int v = 0; v < 7; v++) {
            ull xd; DUP2(xd, xr[v]);
            #pragma unroll
            for (int k = 0; k < 10; k++) FMA2(acc2[k], xd, wr[v*20 + k]);
        }
      }
    #pragma unroll
    for (int k = 0; k < 10; k++) {
        float2 f = *reinterpret_cast<float2*>(&acc2[k]);
        int oc0 = half*20 + 2*k;
        #pragma unroll
        for (int h = 0; h < 2; h++) {
            int oc = oc0 + h;
            float val = h ? f.y : f.x;
            if (oc < 24) g_q[((b*24 + oc)*H2 + oy)*H2 + ox]      = val;
            else         g_v[((b*16 + (oc-24))*H2 + oy)*H2 + ox] = val;
        }
    }
}

// ===========================================================================
// Pre-pass: q -> 4 shifted bf16 hi/lo copies. grid (384, 4=qp)
// ===========================================================================
__global__ __launch_bounds__(256) void k_cvt_q()
{
    const int bx = blockIdx.x, qp = blockIdx.y;
    const float* Q = g_q + bx*H2*H2;
    __nv_bfloat16* oh = g_qsh + ((size_t)(qp*2+0)*384 + bx)*112*128;
    __nv_bfloat16* ol = g_qsh + ((size_t)(qp*2+1)*384 + bx)*112*128;
    for (int t = threadIdx.x; t < 112*128; t += 256) {
        int y = t >> 7, j = t & 127;
        int jj = j + 2*qp;
        float v = (jj >= 3 && jj < 115) ? Q[y*H2 + (jj-3)] : 0.f;
        __nv_bfloat16 h = __float2bfloat16(v);
        oh[t] = h;
        ol[t] = __float2bfloat16(v - __bfloat162float(h));
    }
}

// Pre-pass: x -> 7 phase-deinterleaved bf16 hi/lo copies. grid (48, 7=v)
__global__ __launch_bounds__(256) void k_cvt_x(const float* __restrict__ x)
{
    const int bc = blockIdx.x, v = blockIdx.y;
    const float* X = x + bc*Hn*Wn;
    __nv_bfloat16* oh = g_xsh + ((size_t)(v*2+0)*48 + bc)*224*128;
    __nv_bfloat16* ol = g_xsh + ((size_t)(v*2+1)*48 + bc)*224*128;
    for (int t = threadIdx.x; t < 224*128; t += 256) {
        int y = t >> 7, j = t & 127;
        int col = 2*j + v;
        float val = (col >= 3 && col < 227) ? X[y*Wn + (col-3)] : 0.f;
        __nv_bfloat16 h = __float2bfloat16(val);
        oh[t] = h;
        ol[t] = __float2bfloat16(val - __bfloat162float(h));
    }
}

// ===========================================================================
// Kernel S via mma.sync, cp.async double-buffered.
// MMA order: B fragments hoisted, splits-outer -> acc reuse distance 8 MMAs.
// ===========================================================================
#define SM_AH    0
#define SM_AL    32768
#define SM_BH    65536
#define SM_BL    81920
#define BUFSTRIDE 98304
#define SM_TOT   (2*BUFSTRIDE)    // 192 KB

extern __shared__ char dsm[];

__device__ __forceinline__ void fill_tiles(uint32_t smem, uint32_t bufbase,
        int ky, int tid, const char* qbase, const char* xbase)
{
    #pragma unroll
    for (int k = 0; k < 16; k++) {
        int idx = tid + 256*k;
        int ch = idx & 15, m = (idx >> 4) & 127, mat = idx >> 11;
        int qp = m & 3, p = (m >> 2) & 3, qc = m >> 4;
        int r = ky + 2*p - 3;
        unsigned ok = ((unsigned)r < 112u);
        const char* src = qbase + (qp*2+mat)*QSH_MATSTRIDE + qc*QSH_QCSTRIDE
                        + (ok ? r : 0)*256 + ch*16;
        uint32_t dst = smem + bufbase + (mat ? SM_AL : SM_AH)
                     + m*256 + ((ch ^ (m & 7))*16);
        CP_ASYNC16(dst, src, ok ? 16u : 0u);
    }
    #pragma unroll
    for (int k = 0; k < 8; k++) {
        int idx = tid + 256*k;
        int ch = idx & 15, n = (idx >> 4) & 63, mat = idx >> 10;
        int u = n >> 3, v = n & 7;
        int r = 2*ky - 3 + u;
        unsigned ok = (v < 7) && (u < 7) && ((unsigned)r < 224u);
        const char* src = xbase + ((ok ? v : 0)*2+mat)*XSH_MATSTRIDE
                        + (ok ? r : 0)*256 + ch*16;
        uint32_t dst = smem + bufbase + (mat ? SM_BL : SM_BH)
                     + n*256 + ((ch ^ (n & 7))*16);
        CP_ASYNC16(dst, src, ok ? 16u : 0u);
    }
}

__global__ __launch_bounds__(256) void k_S_mma()
{
    const uint32_t smem = smem_to_u32(dsm);
    const int tid = threadIdx.x, w = tid >> 5, lane = tid & 31;
    const int bx = blockIdx.x;               // 144 = (b,i,c), c fastest
    const int c = bx % 3, i = (bx/3) % 3, b = bx/9;
    const int bi8 = (b*3 + i)*8, bc = b*3 + c;

    const char* qbase = (const char*)g_qsh + (size_t)bi8*QSH_QCSTRIDE;
    const char* xbase = (const char*)g_xsh + (size_t)bc*XSH_BCSTRIDE;

    float acc[8][4];
    #pragma unroll
    for (int n = 0; n < 8; n++)
      #pragma unroll
      for (int e = 0; e < 4; e++) acc[n][e] = 0.f;

    const int rA = w*16 + (lane & 15);
    const uint32_t aAoff = rA*256;
    const uint32_t aArx  = (rA & 7)*16;
    const int hA = (lane >> 4) & 1;
    const int rBo = (lane & 7) + ((lane & 16) >> 1);
    const uint32_t bBrx = (lane & 7)*16;
    const int hB = (lane >> 3) & 1;

    fill_tiles(smem, 0, 0, tid, qbase, xbase);          CP_COMMIT();
    fill_tiles(smem, BUFSTRIDE, 1, tid, qbase, xbase);  CP_COMMIT();

    for (int ky = 0; ky < 112; ky++) {
        if (ky == 111) { CP_WAIT0(); } else { CP_WAIT1(); }
        __syncthreads();                  // buf[ky&1] visible to all warps

        const uint32_t base = smem + (uint32_t)(ky & 1)*BUFSTRIDE;
        const uint32_t aAddrH = base + SM_AH + aAoff;
        const uint32_t aAddrL = base + SM_AL + aAoff;

        #pragma unroll 1
        for (int ks = 0; ks < 7; ks++) {
            const uint32_t cA = (uint32_t)(2*ks + hA)*16;
            uint32_t ah[4], al[4];
            LDSM_X4(ah[0],ah[1],ah[2],ah[3], aAddrH + (cA ^ aArx));
            LDSM_X4(al[0],al[1],al[2],al[3], aAddrL + (cA ^ aArx));
            const uint32_t cB = (uint32_t)(2*ks + hB)*16;
            uint32_t bh[4][4], bl[4][4];
            #pragma unroll
            for (int nbp = 0; nbp < 4; nbp++) {
                const uint32_t rbB = (uint32_t)(nbp*16 + rBo)*256 + (cB ^ bBrx);
                LDSM_X4(bh[nbp][0],bh[nbp][1],bh[nbp][2],bh[nbp][3], base + SM_BH + rbB);
                LDSM_X4(bl[nbp][0],bl[nbp][1],bl[nbp][2],bl[nbp][3], base + SM_BL + rbB);
            }
            // splits-outer: same-acc reuse distance = 8 MMAs
            #pragma unroll
            for (int nbp = 0; nbp < 4; nbp++) {
                MMA16816(acc[2*nbp],   ah, bh[nbp][0], bh[nbp][1]);
                MMA16816(acc[2*nbp+1], ah, bh[nbp][2], bh[nbp][3]);
            }
            #pragma unroll
            for (int nbp = 0; nbp < 4; nbp++) {
                MMA16816(acc[2*nbp],   ah, bl[nbp][0], bl[nbp][1]);
                MMA16816(acc[2*nbp+1], ah, bl[nbp][2], bl[nbp][3]);
            }
            #pragma unroll
            for (int nbp = 0; nbp < 4; nbp++) {
                MMA16816(acc[2*nbp],   al, bh[nbp][0], bh[nbp][1]);
                MMA16816(acc[2*nbp+1], al, bh[nbp][2], bh[nbp][3]);
            }
        }
        __syncthreads();                  // all reads of buf[ky&1] done
        if (ky + 2 < 112) {
            fill_tiles(smem, (uint32_t)(ky & 1)*BUFSTRIDE, ky + 2, tid, qbase, xbase);
            CP_COMMIT();
        }
    }

    // ---- epilogue: scatter live fragments to g_S
    const int m0 = w*16;
    #pragma unroll
    for (int nb = 0; nb < 7; nb++) {
        const int ncol = nb*8 + 2*(lane & 3);
        #pragma unroll
        for (int hf = 0; hf < 2; hf++) {
            int m = m0 + (lane >> 2) + hf*8;
            int qc = m >> 4, pq = m & 15;
            float* So = g_S + ((((b*3+i)*8 + qc)*3 + c)*784 + pq*49);
            #pragma unroll
            for (int e = 0; e < 2; e++) {
                int n = ncol + e;
                int vv = n & 7;
                if (vv < 7) So[nb*7 + vv] = acc[nb][hf*2 + e];
            }
        }
    }
}

// ===========================================================================
// Kernel Qs: clipped window sums of q. grid 384 = (b,i,qc)
// ===========================================================================
__global__ __launch_bounds__(128) void k_qs()
{
    __shared__ float cs[4][114];
    const int bx = blockIdx.x;
    const float* Q = g_q + bx*H2*H2;
    const int tid = threadIdx.x;
    if (tid < 112) {
        float full=0.f, e0=0.f,e1=0.f,e2=0.f,e109=0.f,e110=0.f,e111=0.f;
        for (int y = 0; y < 112; y++) {
            float v = Q[y*H2 + tid];
            full += v;
            if (y==0) e0=v; else if (y==1) e1=v; else if (y==2) e2=v;
            else if (y==109) e109=v; else if (y==110) e110=v; else if (y==111) e111=v;
        }
        cs[0][tid] = full - e109 - e110 - e111;
        cs[1][tid] = full - e111;
        cs[2][tid] = full - e0;
        cs[3][tid] = full - e0 - e1 - e2;
    }
    __syncthreads();
    if (tid < 16) {
        int p = tid >> 2, qx = tid & 3;
        int xs_ = (qx <= 1) ? 0 : (qx == 2 ? 1 : 3);
        int xe_ = (qx == 0) ? 109 : (qx == 1 ? 111 : 112);
        float s = 0.f;
        for (int xc = xs_; xc < xe_; xc++) s += cs[p][xc];
        g_Qs[bx*16 + tid] = s;
    }
}

// ===========================================================================
// Kernel a: grid 768 = (b,i,vc); 256 thr = 16 K-slices x 16 pq
// ===========================================================================
__global__ __launch_bounds__(256) void k_a(const float* __restrict__ Wk,
                                           const float* __restrict__ bk)
{
    const int bx = blockIdx.x;
    const int vc = bx & 15, bi = bx >> 4;
    const int i = bi % 3;
    const int tid = threadIdx.x;
    const int s = tid & 15, pq = tid >> 4;
    const float* Sb = g_S + bi*24*784;
    const float* Wb = Wk + i*(VCn*QCn*ICn*49) + vc*(QCn*ICn*49);
    float acc = 0.f;
    #pragma unroll 1
    for (int qcc = 0; qcc < 24; qcc++) {
        const float* Sp = Sb + qcc*784 + pq*49;
        const float* Wp = Wb + qcc*49;
        #pragma unroll
        for (int uv = s; uv < 49; uv += 16) acc += Wp[uv]*Sp[uv];
    }
    #pragma unroll
    for (int o = 8; o; o >>= 1) acc += __shfl_down_sync(0xffffffffu, acc, o, 16);
    if (s == 0) {
        const float* Qsb = g_Qs + bi*8*16;
        float bterm = 0.f;
        #pragma unroll
        for (int qc = 0; qc < 8; qc++)
            bterm += bk[(i*16+vc)*8+qc] * Qsb[qc*16+pq];
        g_a[bi*256 + vc*16 + pq] = acc + bterm;
    }
}

// ===========================================================================
// Kernel o: o[b,i,58,58] = dynconv(v[b], a[b,i]); grid (48, 14)
// ===========================================================================
__global__ __launch_bounds__(256) void k_o(float* __restrict__ out)
{
    __shared__ float as_[256];
    const int bx = blockIdx.x;
    const int b = bx/3;
    const int tid = threadIdx.x;
    as_[tid] = g_a[bx*256 + tid];
    __syncthreads();

    const int idx = blockIdx.y*256 + tid;
    if (idx >= 58*58) return;
    const int oy = idx/58, ox = idx%58;
    const float* vb = g_v + b*16*H2*H2;
    float acc = 0.f;
    for (int vc = 0; vc < 16; vc++) {
        const float* vp = vb + vc*H2*H2;
        const float* ap = &as_[vc*16];
        #pragma unroll
        for (int ky = 0; ky < 4; ky++) {
            int r = 2*oy - 3 + ky;
            if (r < 0 || r >= H2) continue;
            #pragma unroll
            for (int kx = 0; kx < 4; kx++) {
                int cc = 2*ox - 3 + kx;
                if (cc < 0 || cc >= H2) continue;
                acc += ap[ky*4+kx] * vp[r*H2 + cc];
            }
        }
    }
    out[bx*3364 + idx] = acc;
}

extern "C" void kernel_launch(void* const* d_in, const int* in_sizes, int n_in,
                              void* d_out, int out_size)
{
    const float* x  = (const float*)d_in[0];
    const float* Wq = (const float*)d_in[1];
    const float* bq = (const float*)d_in[2];
    const float* Wk = (const float*)d_in[3];
    const float* bk = (const float*)d_in[4];
    const float* Wv = (const float*)d_in[5];
    const float* bv = (const float*)d_in[6];
    float* out = (float*)d_out;

    cudaFuncSetAttribute(k_S_mma, cudaFuncAttributeMaxDynamicSharedMemorySize, SM_TOT);

    k_convqv<<<dim3(112,16), 224>>>(x, Wq, bq, Wv, bv);
    k_cvt_q <<<dim3(384,4), 256>>>();
    k_cvt_x <<<dim3(48,7), 256>>>(x);
    k_S_mma <<<144, 256, SM_TOT>>>();
    k_qs    <<<384, 128>>>();
    k_a     <<<768, 256>>>(Wk, bk);
    k_o     <<<dim3(48,14), 256>>>(out);
}

// round 15
// speedup vs baseline: 1.0132x; 1.0132x over previous
#include <cuda_runtime.h>
#include <cuda_bf16.h>
#include <stdint.h>

typedef unsigned long long ull;

#define Bn  16
#define ICn 3
#define QCn 8
#define VCn 16
#define Hn  224
#define Wn  224
#define H2  112

// ---- scratch: device globals (no runtime allocation allowed) ----
__device__ float g_q [Bn*24*H2*H2];          // [b][i*8+qc][112][112]
__device__ float g_v [Bn*16*H2*H2];          // [b][vc][112][112]
__device__ float g_S [1152*784];             // [(b,i,qc,c)][pq*49+uv]
__device__ float g_Qs[Bn*ICn*QCn*16];        // [(b,i,qc)][pq]
__device__ float g_a [Bn*ICn*VCn*16];        // [(b,i)][vc*16+pq]
// Pre-shifted bf16 operands, rows padded to 128 elems (256 B):
//  g_qsh[qp][mat][(b,i,qc)][y][j] = hi/lo( q_pad[y][j+2qp] )
//  g_xsh[v ][mat][(b,c)  ][y][j] = hi/lo( x_pad[y][2j+v] )
__device__ __align__(16) __nv_bfloat16 g_qsh[4*2*384*112*128];
__device__ __align__(16) __nv_bfloat16 g_xsh[7*2*48*224*128];

#define QSH_MATSTRIDE 11010048   // 384*112*256 bytes
#define QSH_QCSTRIDE  28672      // 112*256
#define XSH_MATSTRIDE 2752512    // 48*224*256 bytes
#define XSH_BCSTRIDE  57344      // 224*256

#define FMA2(d,a,b) asm("fma.rn.f32x2 %0, %1, %2, %0;" : "+l"(d) : "l"(a), "l"(b))
#define DUP2(d,s)   asm("mov.b64 %0, {%1, %1};" : "=l"(d) : "f"(s))

__device__ __forceinline__ uint32_t smem_to_u32(const void* p) {
    uint32_t a;
    asm("{ .reg .u64 t; cvta.to.shared.u64 t, %1; cvt.u32.u64 %0, t; }" : "=r"(a) : "l"(p));
    return a;
}

#define LDSM_X4(r0,r1,r2,r3,addr) \
    asm volatile("ldmatrix.sync.aligned.m8n8.x4.shared.b16 {%0,%1,%2,%3}, [%4];" \
        : "=r"(r0),"=r"(r1),"=r"(r2),"=r"(r3) : "r"(addr))

#define MMA16816(d,a,b0,b1) \
    asm volatile("mma.sync.aligned.m16n8k16.row.col.f32.bf16.bf16.f32 " \
        "{%0,%1,%2,%3}, {%4,%5,%6,%7}, {%8,%9}, {%0,%1,%2,%3};" \
        : "+f"((d)[0]),"+f"((d)[1]),"+f"((d)[2]),"+f"((d)[3]) \
        : "r"((a)[0]),"r"((a)[1]),"r"((a)[2]),"r"((a)[3]), "r"(b0),"r"(b1))

#define CP_ASYNC16(dst, src, sz) \
    asm volatile("cp.async.cg.shared.global [%0], [%1], 16, %2;" \
        :: "r"(dst), "l"(src), "r"(sz) : "memory")
#define CP_COMMIT()  asm volatile("cp.async.commit_group;" ::: "memory")
#define CP_WAIT1()   asm volatile("cp.async.wait_group 1;" ::: "memory")
#define CP_WAIT0()   asm volatile("cp.async.wait_group 0;" ::: "memory")

// ===========================================================================
// Kernel A: fused static convs q (24 ch) + v (16 ch), stride 2, pad 3.
// ===========================================================================
__global__ __launch_bounds__(224) void k_convqv(
    const float* __restrict__ x,
    const float* __restrict__ Wq, const float* __restrict__ bq,
    const float* __restrict__ Wv, const float* __restrict__ bv)
{
    __shared__ __align__(16) float xs[3*7*232];
    __shared__ __align__(16) float ws[147*40];
    __shared__ __align__(16) float bs[40];
    const int oy = blockIdx.x, b = blockIdx.y;
    const int tid = threadIdx.x;

    for (int t = tid; t < 24*147; t += 224) { int oc=t/147, cuv=t%147; ws[cuv*40+oc]    = Wq[t]; }
    for (int t = tid; t < 16*147; t += 224) { int oc=t/147, cuv=t%147; ws[cuv*40+24+oc] = Wv[t]; }
    if (tid < 24) bs[tid] = bq[tid];
    else if (tid < 40) bs[tid] = bv[tid-24];

    const float* xb = x + b*ICn*Hn*Wn;
    for (int t = tid; t < 3*7*232; t += 224) {
        int cc = t/(7*232), r = (t/232)%7, j = t%232;
        int row = 2*oy - 3 + r, col = j - 3;
        float v = 0.f;
        if (row >= 0 && row < Hn && col >= 0 && col < Wn) v = xb[(cc*Hn+row)*Wn + col];
        xs[t] = v;
    }
    __syncthreads();

    const int half = tid/112, ox = tid%112;
    ull acc2[10];
    {
        const float2* b2 = reinterpret_cast<const float2*>(bs + half*20);
        #pragma unroll
        for (int k = 0; k < 10; k++) {
            float2 t = b2[k];
            asm("mov.b64 %0, {%1, %2};" : "=l"(acc2[k]) : "f"(t.x), "f"(t.y));
        }
    }
    #pragma unroll 1
    for (int cc = 0; cc < 3; cc++)
      #pragma unroll 1
      for (int u = 0; u < 7; u++) {
        const float* xr = &xs[(cc*7+u)*232 + 2*ox];
        const ull*  wr = reinterpret_cast<const ull*>(&ws[(cc*49+u*7)*40 + half*20]);
        #pragma unroll
        for (int v = 0; v < 7; v++) {
            ull xd; DUP2(xd, xr[v]);
            #pragma unroll
            for (int k = 0; k < 10; k++) FMA2(acc2[k], xd, wr[v*20 + k]);
        }
      }
    #pragma unroll
    for (int k = 0; k < 10; k++) {
        float2 f = *reinterpret_cast<float2*>(&acc2[k]);
        int oc0 = half*20 + 2*k;
        #pragma unroll
        for (int h = 0; h < 2; h++) {
            int oc = oc0 + h;
            float val = h ? f.y : f.x;
            if (oc < 24) g_q[((b*24 + oc)*H2 + oy)*H2 + ox]      = val;
            else         g_v[((b*16 + (oc-24))*H2 + oy)*H2 + ox] = val;
        }
    }
}

// ===========================================================================
// Pre-pass: q -> 4 shifted bf16 hi/lo copies. grid (384, 4=qp)
// ===========================================================================
__global__ __launch_bounds__(256) void k_cvt_q()
{
    const int bx = blockIdx.x, qp = blockIdx.y;
    const float* Q = g_q + bx*H2*H2;
    __nv_bfloat16* oh = g_qsh + ((size_t)(qp*2+0)*384 + bx)*112*128;
    __nv_bfloat16* ol = g_qsh + ((size_t)(qp*2+1)*384 + bx)*112*128;
    for (int t = threadIdx.x; t < 112*128; t += 256) {
        int y = t >> 7, j = t & 127;
        int jj = j + 2*qp;
        float v = (jj >= 3 && jj < 115) ? Q[y*H2 + (jj-3)] : 0.f;
        __nv_bfloat16 h = __float2bfloat16(v);
        oh[t] = h;
        ol[t] = __float2bfloat16(v - __bfloat162float(h));
    }
}

// Pre-pass: x -> 7 phase-deinterleaved bf16 hi/lo copies. grid (48, 7=v)
__global__ __launch_bounds__(256) void k_cvt_x(const float* __restrict__ x)
{
    const int bc = blockIdx.x, v = blockIdx.y;
    const float* X = x + bc*Hn*Wn;
    __nv_bfloat16* oh = g_xsh + ((size_t)(v*2+0)*48 + bc)*224*128;
    __nv_bfloat16* ol = g_xsh + ((size_t)(v*2+1)*48 + bc)*224*128;
    for (int t = threadIdx.x; t < 224*128; t += 256) {
        int y = t >> 7, j = t & 127;
        int col = 2*j + v;
        float val = (col >= 3 && col < 227) ? X[y*Wn + (col-3)] : 0.f;
        __nv_bfloat16 h = __float2bfloat16(val);
        oh[t] = h;
        ol[t] = __float2bfloat16(val - __bfloat162float(h));
    }
}

// ===========================================================================
// Kernel S via mma.sync, cp.async double-buffered.
// 512 threads / 16 warps: warp = (M-slice 16 rows) x (N-half 32 cols)
// -> 4 warps per SMSP to hide ldmatrix/HMMA latency.
// ===========================================================================
#define SM_AH    0
#define SM_AL    32768
#define SM_BH    65536
#define SM_BL    81920
#define BUFSTRIDE 98304
#define SM_TOT   (2*BUFSTRIDE)    // 192 KB

extern __shared__ char dsm[];

__device__ __forceinline__ void fill_tiles(uint32_t smem, uint32_t bufbase,
        int ky, int tid, const char* qbase, const char* xbase)
{
    // A: 2 mats x 128 rows x 16 chunks = 4096 cp.asyncs; 512 thr -> 8 each
    #pragma unroll
    for (int k = 0; k < 8; k++) {
        int idx = tid + 512*k;
        int ch = idx & 15, m = (idx >> 4) & 127, mat = idx >> 11;
        int qp = m & 3, p = (m >> 2) & 3, qc = m >> 4;
        int r = ky + 2*p - 3;
        unsigned ok = ((unsigned)r < 112u);
        const char* src = qbase + (qp*2+mat)*QSH_MATSTRIDE + qc*QSH_QCSTRIDE
                        + (ok ? r : 0)*256 + ch*16;
        uint32_t dst = smem + bufbase + (mat ? SM_AL : SM_AH)
                     + m*256 + ((ch ^ (m & 7))*16);
        CP_ASYNC16(dst, src, ok ? 16u : 0u);
    }
    // B: 2 mats x 64 rows x 16 chunks = 2048; 512 thr -> 4 each
    #pragma unroll
    for (int k = 0; k < 4; k++) {
        int idx = tid + 512*k;
        int ch = idx & 15, n = (idx >> 4) & 63, mat = idx >> 10;
        int u = n >> 3, v = n & 7;
        int r = 2*ky - 3 + u;
        unsigned ok = (v < 7) && (u < 7) && ((unsigned)r < 224u);
        const char* src = xbase + ((ok ? v : 0)*2+mat)*XSH_MATSTRIDE
                        + (ok ? r : 0)*256 + ch*16;
        uint32_t dst = smem + bufbase + (mat ? SM_BL : SM_BH)
                     + n*256 + ((ch ^ (n & 7))*16);
        CP_ASYNC16(dst, src, ok ? 16u : 0u);
    }
}

__global__ __launch_bounds__(512) void k_S_mma()
{
    const uint32_t smem = smem_to_u32(dsm);
    const int tid = threadIdx.x, w = tid >> 5, lane = tid & 31;
    const int mslice = w & 7, nhalf = w >> 3;
    const int bx = blockIdx.x;               // 144 = (b,i,c), c fastest
    const int c = bx % 3, i = (bx/3) % 3, b = bx/9;
    const int bi8 = (b*3 + i)*8, bc = b*3 + c;

    const char* qbase = (const char*)g_qsh + (size_t)bi8*QSH_QCSTRIDE;
    const char* xbase = (const char*)g_xsh + (size_t)bc*XSH_BCSTRIDE;

    float acc[4][4];
    #pragma unroll
    for (int n = 0; n < 4; n++)
      #pragma unroll
      for (int e = 0; e < 4; e++) acc[n][e] = 0.f;

    const int rA = mslice*16 + (lane & 15);
    const uint32_t aAoff = rA*256;
    const uint32_t aArx  = (rA & 7)*16;
    const int hA = (lane >> 4) & 1;
    const int rBo = (lane & 7) + ((lane & 16) >> 1);
    const uint32_t bBrx = (lane & 7)*16;
    const int hB = (lane >> 3) & 1;

    fill_tiles(smem, 0, 0, tid, qbase, xbase);          CP_COMMIT();
    fill_tiles(smem, BUFSTRIDE, 1, tid, qbase, xbase);  CP_COMMIT();

    for (int ky = 0; ky < 112; ky++) {
        if (ky == 111) { CP_WAIT0(); } else { CP_WAIT1(); }
        __syncthreads();                  // buf[ky&1] visible to all warps

        const uint32_t base = smem + (uint32_t)(ky & 1)*BUFSTRIDE;
        const uint32_t aAddrH = base + SM_AH + aAoff;
        const uint32_t aAddrL = base + SM_AL + aAoff;

        #pragma unroll 1
        for (int ks = 0; ks < 7; ks++) {
            const uint32_t cA = (uint32_t)(2*ks + hA)*16;
            uint32_t ah[4], al[4];
            LDSM_X4(ah[0],ah[1],ah[2],ah[3], aAddrH + (cA ^ aArx));
            LDSM_X4(al[0],al[1],al[2],al[3], aAddrL + (cA ^ aArx));
            const uint32_t cB = (uint32_t)(2*ks + hB)*16;
            uint32_t bh[2][4], bl[2][4];
            #pragma unroll
            for (int nl = 0; nl < 2; nl++) {
                const int nbp = nhalf*2 + nl;
                const uint32_t rbB = (uint32_t)(nbp*16 + rBo)*256 + (cB ^ bBrx);
                LDSM_X4(bh[nl][0],bh[nl][1],bh[nl][2],bh[nl][3], base + SM_BH + rbB);
                LDSM_X4(bl[nl][0],bl[nl][1],bl[nl][2],bl[nl][3], base + SM_BL + rbB);
            }
            #pragma unroll
            for (int nl = 0; nl < 2; nl++) {
                MMA16816(acc[2*nl],   ah, bh[nl][0], bh[nl][1]);
                MMA16816(acc[2*nl+1], ah, bh[nl][2], bh[nl][3]);
            }
            #pragma unroll
            for (int nl = 0; nl < 2; nl++) {
                MMA16816(acc[2*nl],   ah, bl[nl][0], bl[nl][1]);
                MMA16816(acc[2*nl+1], ah, bl[nl][2], bl[nl][3]);
            }
            #pragma unroll
            for (int nl = 0; nl < 2; nl++) {
                MMA16816(acc[2*nl],   al, bh[nl][0], bh[nl][1]);
                MMA16816(acc[2*nl+1], al, bh[nl][2], bh[nl][3]);
            }
        }
        __syncthreads();                  // all reads of buf[ky&1] done
        if (ky + 2 < 112) {
            fill_tiles(smem, (uint32_t)(ky & 1)*BUFSTRIDE, ky + 2, tid, qbase, xbase);
            CP_COMMIT();
        }
    }

    // ---- epilogue: scatter live fragments to g_S (dead: nb==7 / vv==7)
    const int m0 = mslice*16;
    #pragma unroll
    for (int nl = 0; nl < 4; nl++) {
        const int nb = nhalf*4 + nl;
        if (nb == 7) continue;
        const int ncol = nb*8 + 2*(lane & 3);
        #pragma unroll
        for (int hf = 0; hf < 2; hf++) {
            int m = m0 + (lane >> 2) + hf*8;
            int qc = m >> 4, pq = m & 15;
            float* So = g_S + ((((b*3+i)*8 + qc)*3 + c)*784 + pq*49);
            #pragma unroll
            for (int e = 0; e < 2; e++) {
                int n = ncol + e;
                int vv = n & 7;
                if (vv < 7) So[nb*7 + vv] = acc[nl][hf*2 + e];
            }
        }
    }
}

// ===========================================================================
// Kernel Qs: clipped window sums of q. grid 384 = (b,i,qc)
// ===========================================================================
__global__ __launch_bounds__(128) void k_qs()
{
    __shared__ float cs[4][114];
    const int bx = blockIdx.x;
    const float* Q = g_q + bx*H2*H2;
    const int tid = threadIdx.x;
    if (tid < 112) {
        float full=0.f, e0=0.f,e1=0.f,e2=0.f,e109=0.f,e110=0.f,e111=0.f;
        for (int y = 0; y < 112; y++) {
            float v = Q[y*H2 + tid];
            full += v;
            if (y==0) e0=v; else if (y==1) e1=v; else if (y==2) e2=v;
            else if (y==109) e109=v; else if (y==110) e110=v; else if (y==111) e111=v;
        }
        cs[0][tid] = full - e109 - e110 - e111;
        cs[1][tid] = full - e111;
        cs[2][tid] = full - e0;
        cs[3][tid] = full - e0 - e1 - e2;
    }
    __syncthreads();
    if (tid < 16) {
        int p = tid >> 2, qx = tid & 3;
        int xs_ = (qx <= 1) ? 0 : (qx == 2 ? 1 : 3);
        int xe_ = (qx == 0) ? 109 : (qx == 1 ? 111 : 112);
        float s = 0.f;
        for (int xc = xs_; xc < xe_; xc++) s += cs[p][xc];
        g_Qs[bx*16 + tid] = s;
    }
}

// ===========================================================================
// Kernel a: grid 768 = (b,i,vc); 256 thr = 16 K-slices x 16 pq
// ===========================================================================
__global__ __launch_bounds__(256) void k_a(const float* __restrict__ Wk,
                                           const float* __restrict__ bk)
{
    const int bx = blockIdx.x;
    const int vc = bx & 15, bi = bx >> 4;
    const int i = bi % 3;
    const int tid = threadIdx.x;
    const int s = tid & 15, pq = tid >> 4;
    const float* Sb = g_S + bi*24*784;
    const float* Wb = Wk + i*(VCn*QCn*ICn*49) + vc*(QCn*ICn*49);
    float acc = 0.f;
    #pragma unroll 1
    for (int qcc = 0; qcc < 24; qcc++) {
        const float* Sp = Sb + qcc*784 + pq*49;
        const float* Wp = Wb + qcc*49;
        #pragma unroll
        for (int uv = s; uv < 49; uv += 16) acc += Wp[uv]*Sp[uv];
    }
    #pragma unroll
    for (int o = 8; o; o >>= 1) acc += __shfl_down_sync(0xffffffffu, acc, o, 16);
    if (s == 0) {
        const float* Qsb = g_Qs + bi*8*16;
        float bterm = 0.f;
        #pragma unroll
        for (int qc = 0; qc < 8; qc++)
            bterm += bk[(i*16+vc)*8+qc] * Qsb[qc*16+pq];
        g_a[bi*256 + vc*16 + pq] = acc + bterm;
    }
}

// ===========================================================================
// Kernel o: o[b,i,58,58] = dynconv(v[b], a[b,i]); grid (48, 14)
// ===========================================================================
__global__ __launch_bounds__(256) void k_o(float* __restrict__ out)
{
    __shared__ float as_[256];
    const int bx = blockIdx.x;
    const int b = bx/3;
    const int tid = threadIdx.x;
    as_[tid] = g_a[bx*256 + tid];
    __syncthreads();

    const int idx = blockIdx.y*256 + tid;
    if (idx >= 58*58) return;
    const int oy = idx/58, ox = idx%58;
    const float* vb = g_v + b*16*H2*H2;
    float acc = 0.f;
    for (int vc = 0; vc < 16; vc++) {
        const float* vp = vb + vc*H2*H2;
        const float* ap = &as_[vc*16];
        #pragma unroll
        for (int ky = 0; ky < 4; ky++) {
            int r = 2*oy - 3 + ky;
            if (r < 0 || r >= H2) continue;
            #pragma unroll
            for (int kx = 0; kx < 4; kx++) {
                int cc = 2*ox - 3 + kx;
                if (cc < 0 || cc >= H2) continue;
                acc += ap[ky*4+kx] * vp[r*H2 + cc];
            }
        }
    }
    out[bx*3364 + idx] = acc;
}

extern "C" void kernel_launch(void* const* d_in, const int* in_sizes, int n_in,
                              void* d_out, int out_size)
{
    const float* x  = (const float*)d_in[0];
    const float* Wq = (const float*)d_in[1];
    const float* bq = (const float*)d_in[2];
    const float* Wk = (const float*)d_in[3];
    const float* bk = (const float*)d_in[4];
    const float* Wv = (const float*)d_in[5];
    const float* bv = (const float*)d_in[6];
    float* out = (float*)d_out;

    cudaFuncSetAttribute(k_S_mma, cudaFuncAttributeMaxDynamicSharedMemorySize, SM_TOT);

    k_convqv<<<dim3(112,16), 224>>>(x, Wq, bq, Wv, bv);
    k_cvt_q <<<dim3(384,4), 256>>>();
    k_cvt_x <<<dim3(48,7), 256>>>(x);
    k_S_mma <<<144, 512, SM_TOT>>>();
    k_qs    <<<384, 128>>>();
    k_a     <<<768, 256>>>(Wk, bk);
    k_o     <<<dim3(48,14), 256>>>(out);
}

// round 16
// speedup vs baseline: 1.0535x; 1.0398x over previous
#include <cuda_runtime.h>
#include <cuda_bf16.h>
#include <stdint.h>

typedef unsigned long long ull;

#define Bn  16
#define ICn 3
#define QCn 8
#define VCn 16
#define Hn  224
#define Wn  224
#define H2  112

// ---- scratch: device globals (no runtime allocation allowed) ----
__device__ float g_q [Bn*24*H2*H2];          // [b][i*8+qc][112][112]
__device__ float g_v [Bn*16*H2*H2];          // [b][vc][112][112]
__device__ float g_S [1152*784];             // [(b,i,qc,c)][pq*49+uv]
__device__ float g_Qs[Bn*ICn*QCn*16];        // [(b,i,qc)][pq]
__device__ float g_a [Bn*ICn*VCn*16];        // [(b,i)][vc*16+pq]
// Pre-shifted bf16 operands, rows padded to 128 elems (256 B):
//  g_qsh[qp][mat][(b,i,qc)][y][j] = hi/lo( q_pad[y][j+2qp] )
//  g_xsh[v ][mat][(b,c)  ][y][j] = hi/lo( x_pad[y][2j+v] )
__device__ __align__(16) __nv_bfloat16 g_qsh[4*2*384*112*128];
__device__ __align__(16) __nv_bfloat16 g_xsh[7*2*48*224*128];

#define QSH_MATSTRIDE 11010048   // 384*112*256 bytes
#define QSH_QCSTRIDE  28672      // 112*256
#define XSH_MATSTRIDE 2752512    // 48*224*256 bytes
#define XSH_BCSTRIDE  57344      // 224*256

#define FMA2(d,a,b) asm("fma.rn.f32x2 %0, %1, %2, %0;" : "+l"(d) : "l"(a), "l"(b))
#define DUP2(d,s)   asm("mov.b64 %0, {%1, %1};" : "=l"(d) : "f"(s))

__device__ __forceinline__ uint32_t smem_to_u32(const void* p) {
    uint32_t a;
    asm("{ .reg .u64 t; cvta.to.shared.u64 t, %1; cvt.u32.u64 %0, t; }" : "=r"(a) : "l"(p));
    return a;
}

#define LDSM_X4(r0,r1,r2,r3,addr) \
    asm volatile("ldmatrix.sync.aligned.m8n8.x4.shared.b16 {%0,%1,%2,%3}, [%4];" \
        : "=r"(r0),"=r"(r1),"=r"(r2),"=r"(r3) : "r"(addr))

#define MMA16816(d,a,b0,b1) \
    asm volatile("mma.sync.aligned.m16n8k16.row.col.f32.bf16.bf16.f32 " \
        "{%0,%1,%2,%3}, {%4,%5,%6,%7}, {%8,%9}, {%0,%1,%2,%3};" \
        : "+f"((d)[0]),"+f"((d)[1]),"+f"((d)[2]),"+f"((d)[3]) \
        : "r"((a)[0]),"r"((a)[1]),"r"((a)[2]),"r"((a)[3]), "r"(b0),"r"(b1))

#define CP_ASYNC16(dst, src, sz) \
    asm volatile("cp.async.cg.shared.global [%0], [%1], 16, %2;" \
        :: "r"(dst), "l"(src), "r"(sz) : "memory")
#define CP_COMMIT()  asm volatile("cp.async.commit_group;" ::: "memory")
#define CP_WAIT1()   asm volatile("cp.async.wait_group 1;" ::: "memory")
#define CP_WAIT0()   asm volatile("cp.async.wait_group 0;" ::: "memory")

// ===========================================================================
// Kernel A: fused static convs q (24 ch) + v (16 ch), stride 2, pad 3.
// ===========================================================================
__global__ __launch_bounds__(224) void k_convqv(
    const float* __restrict__ x,
    const float* __restrict__ Wq, const float* __restrict__ bq,
    const float* __restrict__ Wv, const float* __restrict__ bv)
{
    __shared__ __align__(16) float xs[3*7*232];
    __shared__ __align__(16) float ws[147*40];
    __shared__ __align__(16) float bs[40];
    const int oy = blockIdx.x, b = blockIdx.y;
    const int tid = threadIdx.x;

    for (int t = tid; t < 24*147; t += 224) { int oc=t/147, cuv=t%147; ws[cuv*40+oc]    = Wq[t]; }
    for (int t = tid; t < 16*147; t += 224) { int oc=t/147, cuv=t%147; ws[cuv*40+24+oc] = Wv[t]; }
    if (tid < 24) bs[tid] = bq[tid];
    else if (tid < 40) bs[tid] = bv[tid-24];

    const float* xb = x + b*ICn*Hn*Wn;
    for (int t = tid; t < 3*7*232; t += 224) {
        int cc = t/(7*232), r = (t/232)%7, j = t%232;
        int row = 2*oy - 3 + r, col = j - 3;
        float v = 0.f;
        if (row >= 0 && row < Hn && col >= 0 && col < Wn) v = xb[(cc*Hn+row)*Wn + col];
        xs[t] = v;
    }
    __syncthreads();

    const int half = tid/112, ox = tid%112;
    ull acc2[10];
    {
        const float2* b2 = reinterpret_cast<const float2*>(bs + half*20);
        #pragma unroll
        for (int k = 0; k < 10; k++) {
            float2 t = b2[k];
            asm("mov.b64 %0, {%1, %2};" : "=l"(acc2[k]) : "f"(t.x), "f"(t.y));
        }
    }
    #pragma unroll 1
    for (int cc = 0; cc < 3; cc++)
      #pragma unroll 1
      for (int u = 0; u < 7; u++) {
        const float* xr = &xs[(cc*7+u)*232 + 2*ox];
        const ull*  wr = reinterpret_cast<const ull*>(&ws[(cc*49+u*7)*40 + half*20]);
        #pragma unroll
        for (int v = 0; v < 7; v++) {
            ull xd; DUP2(xd, xr[v]);
            #pragma unroll
            for (int k = 0; k < 10; k++) FMA2(acc2[k], xd, wr[v*20 + k]);
        }
      }
    #pragma unroll
    for (int k = 0; k < 10; k++) {
        float2 f = *reinterpret_cast<float2*>(&acc2[k]);
        int oc0 = half*20 + 2*k;
        #pragma unroll
        for (int h = 0; h < 2; h++) {
            int oc = oc0 + h;
            float val = h ? f.y : f.x;
            if (oc < 24) g_q[((b*24 + oc)*H2 + oy)*H2 + ox]      = val;
            else         g_v[((b*16 + (oc-24))*H2 + oy)*H2 + ox] = val;
        }
    }
}

// ===========================================================================
// Pre-pass: q -> 4 shifted bf16 hi/lo copies. grid (384, 4=qp)
// ===========================================================================
__global__ __launch_bounds__(256) void k_cvt_q()
{
    const int bx = blockIdx.x, qp = blockIdx.y;
    const float* Q = g_q + bx*H2*H2;
    __nv_bfloat16* oh = g_qsh + ((size_t)(qp*2+0)*384 + bx)*112*128;
    __nv_bfloat16* ol = g_qsh + ((size_t)(qp*2+1)*384 + bx)*112*128;
    for (int t = threadIdx.x; t < 112*128; t += 256) {
        int y = t >> 7, j = t & 127;
        int jj = j + 2*qp;
        float v = (jj >= 3 && jj < 115) ? Q[y*H2 + (jj-3)] : 0.f;
        __nv_bfloat16 h = __float2bfloat16(v);
        oh[t] = h;
        ol[t] = __float2bfloat16(v - __bfloat162float(h));
    }
}

// Pre-pass: x -> 7 phase-deinterleaved bf16 hi/lo copies. grid (48, 7=v)
__global__ __launch_bounds__(256) void k_cvt_x(const float* __restrict__ x)
{
    const int bc = blockIdx.x, v = blockIdx.y;
    const float* X = x + bc*Hn*Wn;
    __nv_bfloat16* oh = g_xsh + ((size_t)(v*2+0)*48 + bc)*224*128;
    __nv_bfloat16* ol = g_xsh + ((size_t)(v*2+1)*48 + bc)*224*128;
    for (int t = threadIdx.x; t < 224*128; t += 256) {
        int y = t >> 7, j = t & 127;
        int col = 2*j + v;
        float val = (col >= 3 && col < 227) ? X[y*Wn + (col-3)] : 0.f;
        __nv_bfloat16 h = __float2bfloat16(val);
        oh[t] = h;
        ol[t] = __float2bfloat16(val - __bfloat162float(h));
    }
}

// ===========================================================================
// Kernel S via mma.sync, cp.async double-buffered.
// 256 threads / 8 warps; warp tile = 32 M-rows x 32 N-cols (4m x 2n grid).
// Per ks per warp: 4 A-LDSM + 4 B-LDSM + 24 MMA -> 3:1 MMA:LDSM, smem reads
// cut from 344 KB/ky to 229 KB/ky (A 2x-, B 4x-redundant instead of 2x/8x).
// ===========================================================================
#define SM_AH    0
#define SM_AL    32768
#define SM_BH    65536
#define SM_BL    81920
#define BUFSTRIDE 98304
#define SM_TOT   (2*BUFSTRIDE)    // 192 KB

extern __shared__ char dsm[];

__device__ __forceinline__ void fill_tiles(uint32_t smem, uint32_t bufbase,
        int ky, int tid, const char* qbase, const char* xbase)
{
    // A: 2 mats x 128 rows x 16 chunks = 4096 cp.asyncs; 256 thr -> 16 each
    #pragma unroll
    for (int k = 0; k < 16; k++) {
        int idx = tid + 256*k;
        int ch = idx & 15, m = (idx >> 4) & 127, mat = idx >> 11;
        int qp = m & 3, p = (m >> 2) & 3, qc = m >> 4;
        int r = ky + 2*p - 3;
        unsigned ok = ((unsigned)r < 112u);
        const char* src = qbase + (qp*2+mat)*QSH_MATSTRIDE + qc*QSH_QCSTRIDE
                        + (ok ? r : 0)*256 + ch*16;
        uint32_t dst = smem + bufbase + (mat ? SM_AL : SM_AH)
                     + m*256 + ((ch ^ (m & 7))*16);
        CP_ASYNC16(dst, src, ok ? 16u : 0u);
    }
    // B: 2 mats x 64 rows x 16 chunks = 2048; 256 thr -> 8 each
    #pragma unroll
    for (int k = 0; k < 8; k++) {
        int idx = tid + 256*k;
        int ch = idx & 15, n = (idx >> 4) & 63, mat = idx >> 10;
        int u = n >> 3, v = n & 7;
        int r = 2*ky - 3 + u;
        unsigned ok = (v < 7) && (u < 7) && ((unsigned)r < 224u);
        const char* src = xbase + ((ok ? v : 0)*2+mat)*XSH_MATSTRIDE
                        + (ok ? r : 0)*256 + ch*16;
        uint32_t dst = smem + bufbase + (mat ? SM_BL : SM_BH)
                     + n*256 + ((ch ^ (n & 7))*16);
        CP_ASYNC16(dst, src, ok ? 16u : 0u);
    }
}

__global__ __launch_bounds__(256) void k_S_mma()
{
    const uint32_t smem = smem_to_u32(dsm);
    const int tid = threadIdx.x, w = tid >> 5, lane = tid & 31;
    const int mslice = w & 3, nhalf = w >> 2;
    const int bx = blockIdx.x;               // 144 = (b,i,c), c fastest
    const int c = bx % 3, i = (bx/3) % 3, b = bx/9;
    const int bi8 = (b*3 + i)*8, bc = b*3 + c;

    const char* qbase = (const char*)g_qsh + (size_t)bi8*QSH_QCSTRIDE;
    const char* xbase = (const char*)g_xsh + (size_t)bc*XSH_BCSTRIDE;

    float acc[2][4][4];                      // [mf][n8][elem]
    #pragma unroll
    for (int mf = 0; mf < 2; mf++)
      #pragma unroll
      for (int n = 0; n < 4; n++)
        #pragma unroll
        for (int e = 0; e < 4; e++) acc[mf][n][e] = 0.f;

    // A: two m16 fragments at rows mslice*32 + mf*16 + (lane&15)
    const int rA0 = mslice*32 + (lane & 15);
    const uint32_t aArx = (rA0 & 7)*16;      // +16 preserves (&7)
    const uint32_t aAoff0 = rA0*256, aAoff1 = (rA0+16)*256;
    const int hA = (lane >> 4) & 1;
    const int rBo = (lane & 7) + ((lane & 16) >> 1);
    const uint32_t bBrx = (lane & 7)*16;
    const int hB = (lane >> 3) & 1;

    fill_tiles(smem, 0, 0, tid, qbase, xbase);          CP_COMMIT();
    fill_tiles(smem, BUFSTRIDE, 1, tid, qbase, xbase);  CP_COMMIT();

    for (int ky = 0; ky < 112; ky++) {
        if (ky == 111) { CP_WAIT0(); } else { CP_WAIT1(); }
        __syncthreads();                  // buf[ky&1] visible to all warps

        const uint32_t base = smem + (uint32_t)(ky & 1)*BUFSTRIDE;

        #pragma unroll 1
        for (int ks = 0; ks < 7; ks++) {
            const uint32_t cA = (uint32_t)(2*ks + hA)*16;
            uint32_t ah[2][4], al[2][4];
            LDSM_X4(ah[0][0],ah[0][1],ah[0][2],ah[0][3], base + SM_AH + aAoff0 + (cA ^ aArx));
            LDSM_X4(ah[1][0],ah[1][1],ah[1][2],ah[1][3], base + SM_AH + aAoff1 + (cA ^ aArx));
            LDSM_X4(al[0][0],al[0][1],al[0][2],al[0][3], base + SM_AL + aAoff0 + (cA ^ aArx));
            LDSM_X4(al[1][0],al[1][1],al[1][2],al[1][3], base + SM_AL + aAoff1 + (cA ^ aArx));
            const uint32_t cB = (uint32_t)(2*ks + hB)*16;
            uint32_t bh[2][4], bl[2][4];
            #pragma unroll
            for (int nl = 0; nl < 2; nl++) {
                const int nbp = nhalf*2 + nl;
                const uint32_t rbB = (uint32_t)(nbp*16 + rBo)*256 + (cB ^ bBrx);
                LDSM_X4(bh[nl][0],bh[nl][1],bh[nl][2],bh[nl][3], base + SM_BH + rbB);
                LDSM_X4(bl[nl][0],bl[nl][1],bl[nl][2],bl[nl][3], base + SM_BL + rbB);
            }
            // pass hh
            #pragma unroll
            for (int mf = 0; mf < 2; mf++)
              #pragma unroll
              for (int nl = 0; nl < 2; nl++) {
                MMA16816(acc[mf][2*nl],   ah[mf], bh[nl][0], bh[nl][1]);
                MMA16816(acc[mf][2*nl+1], ah[mf], bh[nl][2], bh[nl][3]);
              }
            // pass hl
            #pragma unroll
            for (int mf = 0; mf < 2; mf++)
              #pragma unroll
              for (int nl = 0; nl < 2; nl++) {
                MMA16816(acc[mf][2*nl],   ah[mf], bl[nl][0], bl[nl][1]);
                MMA16816(acc[mf][2*nl+1], ah[mf], bl[nl][2], bl[nl][3]);
              }
            // pass lh
            #pragma unroll
            for (int mf = 0; mf < 2; mf++)
              #pragma unroll
              for (int nl = 0; nl < 2; nl++) {
                MMA16816(acc[mf][2*nl],   al[mf], bh[nl][0], bh[nl][1]);
                MMA16816(acc[mf][2*nl+1], al[mf], bh[nl][2], bh[nl][3]);
              }
        }
        __syncthreads();                  // all reads of buf[ky&1] done
        if (ky + 2 < 112) {
            fill_tiles(smem, (uint32_t)(ky & 1)*BUFSTRIDE, ky + 2, tid, qbase, xbase);
            CP_COMMIT();
        }
    }

    // ---- epilogue: scatter live fragments to g_S (dead: nb==7 / vv==7)
    #pragma unroll
    for (int mf = 0; mf < 2; mf++) {
        #pragma unroll
        for (int j = 0; j < 4; j++) {
            const int nb = nhalf*4 + j;
            if (nb == 7) continue;
            const int ncol = nb*8 + 2*(lane & 3);
            #pragma unroll
            for (int hf = 0; hf < 2; hf++) {
                int m = mslice*32 + mf*16 + (lane >> 2) + hf*8;
                int qc = m >> 4, pq = m & 15;
                float* So = g_S + ((((b*3+i)*8 + qc)*3 + c)*784 + pq*49);
                #pragma unroll
                for (int e = 0; e < 2; e++) {
                    int n = ncol + e;
                    int vv = n & 7;
                    if (vv < 7) So[nb*7 + vv] = acc[mf][j][hf*2 + e];
                }
            }
        }
    }
}

// ===========================================================================
// Kernel Qs: clipped window sums of q. grid 384 = (b,i,qc)
// ===========================================================================
__global__ __launch_bounds__(128) void k_qs()
{
    __shared__ float cs[4][114];
    const int bx = blockIdx.x;
    const float* Q = g_q + bx*H2*H2;
    const int tid = threadIdx.x;
    if (tid < 112) {
        float full=0.f, e0=0.f,e1=0.f,e2=0.f,e109=0.f,e110=0.f,e111=0.f;
        for (int y = 0; y < 112; y++) {
            float v = Q[y*H2 + tid];
            full += v;
            if (y==0) e0=v; else if (y==1) e1=v; else if (y==2) e2=v;
            else if (y==109) e109=v; else if (y==110) e110=v; else if (y==111) e111=v;
        }
        cs[0][tid] = full - e109 - e110 - e111;
        cs[1][tid] = full - e111;
        cs[2][tid] = full - e0;
        cs[3][tid] = full - e0 - e1 - e2;
    }
    __syncthreads();
    if (tid < 16) {
        int p = tid >> 2, qx = tid & 3;
        int xs_ = (qx <= 1) ? 0 : (qx == 2 ? 1 : 3);
        int xe_ = (qx == 0) ? 109 : (qx == 1 ? 111 : 112);
        float s = 0.f;
        for (int xc = xs_; xc < xe_; xc++) s += cs[p][xc];
        g_Qs[bx*16 + tid] = s;
    }
}

// ===========================================================================
// Kernel a: grid 768 = (b,i,vc); 256 thr = 16 K-slices x 16 pq
// ===========================================================================
__global__ __launch_bounds__(256) void k_a(const float* __restrict__ Wk,
                                           const float* __restrict__ bk)
{
    const int bx = blockIdx.x;
    const int vc = bx & 15, bi = bx >> 4;
    const int i = bi % 3;
    const int tid = threadIdx.x;
    const int s = tid & 15, pq = tid >> 4;
    const float* Sb = g_S + bi*24*784;
    const float* Wb = Wk + i*(VCn*QCn*ICn*49) + vc*(QCn*ICn*49);
    float acc = 0.f;
    #pragma unroll 1
    for (int qcc = 0; qcc < 24; qcc++) {
        const float* Sp = Sb + qcc*784 + pq*49;
        const float* Wp = Wb + qcc*49;
        #pragma unroll
        for (int uv = s; uv < 49; uv += 16) acc += Wp[uv]*Sp[uv];
    }
    #pragma unroll
    for (int o = 8; o; o >>= 1) acc += __shfl_down_sync(0xffffffffu, acc, o, 16);
    if (s == 0) {
        const float* Qsb = g_Qs + bi*8*16;
        float bterm = 0.f;
        #pragma unroll
        for (int qc = 0; qc < 8; qc++)
            bterm += bk[(i*16+vc)*8+qc] * Qsb[qc*16+pq];
        g_a[bi*256 + vc*16 + pq] = acc + bterm;
    }
}

// ===========================================================================
// Kernel o: o[b,i,58,58] = dynconv(v[b], a[b,i]); grid (48, 14)
// ===========================================================================
__global__ __launch_bounds__(256) void k_o(float* __restrict__ out)
{
    __shared__ float as_[256];
    const int bx = blockIdx.x;
    const int b = bx/3;
    const int tid = threadIdx.x;
    as_[tid] = g_a[bx*256 + tid];
    __syncthreads();

    const int idx = blockIdx.y*256 + tid;
    if (idx >= 58*58) return;
    const int oy = idx/58, ox = idx%58;
    const float* vb = g_v + b*16*H2*H2;
    float acc = 0.f;
    for (int vc = 0; vc < 16; vc++) {
        const float* vp = vb + vc*H2*H2;
        const float* ap = &as_[vc*16];
        #pragma unroll
        for (int ky = 0; ky < 4; ky++) {
            int r = 2*oy - 3 + ky;
            if (r < 0 || r >= H2) continue;
            #pragma unroll
            for (int kx = 0; kx < 4; kx++) {
                int cc = 2*ox - 3 + kx;
                if (cc < 0 || cc >= H2) continue;
                acc += ap[ky*4+kx] * vp[r*H2 + cc];
            }
        }
    }
    out[bx*3364 + idx] = acc;
}

extern "C" void kernel_launch(void* const* d_in, const int* in_sizes, int n_in,
                              void* d_out, int out_size)
{
    const float* x  = (const float*)d_in[0];
    const float* Wq = (const float*)d_in[1];
    const float* bq = (const float*)d_in[2];
    const float* Wk = (const float*)d_in[3];
    const float* bk = (const float*)d_in[4];
    const float* Wv = (const float*)d_in[5];
    const float* bv = (const float*)d_in[6];
    float* out = (float*)d_out;

    cudaFuncSetAttribute(k_S_mma, cudaFuncAttributeMaxDynamicSharedMemorySize, SM_TOT);

    k_convqv<<<dim3(112,16), 224>>>(x, Wq, bq, Wv, bv);
    k_cvt_q <<<dim3(384,4), 256>>>();
    k_cvt_x <<<dim3(48,7), 256>>>(x);
    k_S_mma <<<144, 256, SM_TOT>>>();
    k_qs    <<<384, 128>>>();
    k_a     <<<768, 256>>>(Wk, bk);
    k_o     <<<dim3(48,14), 256>>>(out);
}

// round 17
// speedup vs baseline: 1.1658x; 1.1066x over previous
#include <cuda_runtime.h>
#include <cuda_bf16.h>
#include <stdint.h>

typedef unsigned long long ull;

#define Bn  16
#define ICn 3
#define QCn 8
#define VCn 16
#define Hn  224
#define Wn  224
#define H2  112

// ---- scratch: device globals (no runtime allocation allowed) ----
__device__ float g_q [Bn*24*H2*H2];          // [b][i*8+qc][112][112]
__device__ float g_v [Bn*16*H2*H2];          // [b][vc][112][112]
__device__ float g_S [1152*784];             // [(b,i,qc,c)][pq*49+uv]
__device__ float g_Qs[Bn*ICn*QCn*16];        // [(b,i,qc)][pq]
__device__ float g_a [Bn*ICn*VCn*16];        // [(b,i)][vc*16+pq]
// Pre-shifted bf16 operands, rows padded to 128 elems (256 B). Pad regions
// (never written) rely on CUDA zero-init of __device__ globals.
//  g_qsh[qp][mat][(b*24+oc)][y][j] = hi/lo( q_pad[y][j+2qp] )
//  g_xsh[v ][mat][(b,c)   ][y][j] = hi/lo( x_pad[y][2j+v] )
__device__ __align__(16) __nv_bfloat16 g_qsh[4*2*384*112*128];
__device__ __align__(16) __nv_bfloat16 g_xsh[7*2*48*224*128];

#define QSH_MATSTRIDE 11010048   // 384*112*256 bytes
#define QSH_QCSTRIDE  28672      // 112*256
#define XSH_MATSTRIDE 2752512    // 48*224*256 bytes
#define XSH_BCSTRIDE  57344      // 224*256
#define QSH_PLANE_ELEM 5505024   // 384*112*128 elements
#define XSH_PLANE_ELEM 1376256   // 48*224*128 elements

#define FMA2(d,a,b) asm("fma.rn.f32x2 %0, %1, %2, %0;" : "+l"(d) : "l"(a), "l"(b))
#define DUP2(d,s)   asm("mov.b64 %0, {%1, %1};" : "=l"(d) : "f"(s))

__device__ __forceinline__ uint32_t smem_to_u32(const void* p) {
    uint32_t a;
    asm("{ .reg .u64 t; cvta.to.shared.u64 t, %1; cvt.u32.u64 %0, t; }" : "=r"(a) : "l"(p));
    return a;
}

#define LDSM_X4(r0,r1,r2,r3,addr) \
    asm volatile("ldmatrix.sync.aligned.m8n8.x4.shared.b16 {%0,%1,%2,%3}, [%4];" \
        : "=r"(r0),"=r"(r1),"=r"(r2),"=r"(r3) : "r"(addr))

#define MMA16816(d,a,b0,b1) \
    asm volatile("mma.sync.aligned.m16n8k16.row.col.f32.bf16.bf16.f32 " \
        "{%0,%1,%2,%3}, {%4,%5,%6,%7}, {%8,%9}, {%0,%1,%2,%3};" \
        : "+f"((d)[0]),"+f"((d)[1]),"+f"((d)[2]),"+f"((d)[3]) \
        : "r"((a)[0]),"r"((a)[1]),"r"((a)[2]),"r"((a)[3]), "r"(b0),"r"(b1))

#define CP_ASYNC16(dst, src, sz) \
    asm volatile("cp.async.cg.shared.global [%0], [%1], 16, %2;" \
        :: "r"(dst), "l"(src), "r"(sz) : "memory")
#define CP_COMMIT()  asm volatile("cp.async.commit_group;" ::: "memory")
#define CP_WAIT1()   asm volatile("cp.async.wait_group 1;" ::: "memory")
#define CP_WAIT0()   asm volatile("cp.async.wait_group 0;" ::: "memory")

// ===========================================================================
// Kernel A: fused static convs q (24 ch) + v (16 ch), stride 2, pad 3,
// PLUS inline bf16 hi/lo conversion: q -> g_qsh (4 shifts), x -> g_xsh
// (7 phases, rows 2oy..2oy+1 per block). Replaces k_cvt_q / k_cvt_x.
// ===========================================================================
__global__ __launch_bounds__(224) void k_convqv(
    const float* __restrict__ x,
    const float* __restrict__ Wq, const float* __restrict__ bq,
    const float* __restrict__ Wv, const float* __restrict__ bv)
{
    __shared__ __align__(16) float xs[3*7*232];
    __shared__ __align__(16) float ws[147*40];
    __shared__ __align__(16) float bs[40];
    const int oy = blockIdx.x, b = blockIdx.y;
    const int tid = threadIdx.x;

    for (int t = tid; t < 24*147; t += 224) { int oc=t/147, cuv=t%147; ws[cuv*40+oc]    = Wq[t]; }
    for (int t = tid; t < 16*147; t += 224) { int oc=t/147, cuv=t%147; ws[cuv*40+24+oc] = Wv[t]; }
    if (tid < 24) bs[tid] = bq[tid];
    else if (tid < 40) bs[tid] = bv[tid-24];

    const float* xb = x + b*ICn*Hn*Wn;
    for (int t = tid; t < 3*7*232; t += 224) {
        int cc = t/(7*232), r = (t/232)%7, j = t%232;
        int row = 2*oy - 3 + r, col = j - 3;
        float v = 0.f;
        if (row >= 0 && row < Hn && col >= 0 && col < Wn) v = xb[(cc*Hn+row)*Wn + col];
        xs[t] = v;
    }
    __syncthreads();

    // ---- x -> g_xsh conversion (rows 2oy, 2oy+1), from staged xs rows
    for (int t = tid; t < 2*3*7*128; t += 224) {
        int jq = t & 127;
        int v  = (t >> 7) % 7;
        int cc = (t/(7*128)) % 3;
        int dr = t/(3*7*128);
        int col = 2*jq + v;
        float val = (col < 232) ? xs[(cc*7 + dr + 3)*232 + col] : 0.f;
        __nv_bfloat16 hh = __float2bfloat16(val);
        __nv_bfloat16 ll = __float2bfloat16(val - __bfloat162float(hh));
        size_t basei = (size_t)(b*3 + cc)*224*128 + (size_t)(2*oy + dr)*128 + jq;
        g_xsh[(size_t)(v*2+0)*XSH_PLANE_ELEM + basei] = hh;
        g_xsh[(size_t)(v*2+1)*XSH_PLANE_ELEM + basei] = ll;
    }

    const int half = tid/112, ox = tid%112;
    ull acc2[10];
    {
        const float2* b2 = reinterpret_cast<const float2*>(bs + half*20);
        #pragma unroll
        for (int k = 0; k < 10; k++) {
            float2 t = b2[k];
            asm("mov.b64 %0, {%1, %2};" : "=l"(acc2[k]) : "f"(t.x), "f"(t.y));
        }
    }
    #pragma unroll 1
    for (int cc = 0; cc < 3; cc++)
      #pragma unroll 1
      for (int u = 0; u < 7; u++) {
        const float* xr = &xs[(cc*7+u)*232 + 2*ox];
        const ull*  wr = reinterpret_cast<const ull*>(&ws[(cc*49+u*7)*40 + half*20]);
        #pragma unroll
        for (int v = 0; v < 7; v++) {
            ull xd; DUP2(xd, xr[v]);
            #pragma unroll
            for (int k = 0; k < 10; k++) FMA2(acc2[k], xd, wr[v*20 + k]);
        }
      }
    #pragma unroll
    for (int k = 0; k < 10; k++) {
        float2 f = *reinterpret_cast<float2*>(&acc2[k]);
        int oc0 = half*20 + 2*k;
        #pragma unroll
        for (int h = 0; h < 2; h++) {
            int oc = oc0 + h;
            float val = h ? f.y : f.x;
            if (oc < 24) {
                g_q[((b*24 + oc)*H2 + oy)*H2 + ox] = val;
                // q -> g_qsh (4 shifted copies, hi/lo)
                __nv_bfloat16 hh = __float2bfloat16(val);
                __nv_bfloat16 ll = __float2bfloat16(val - __bfloat162float(hh));
                size_t chbase = (size_t)(b*24 + oc)*112*128 + (size_t)oy*128;
                #pragma unroll
                for (int qp = 0; qp < 4; qp++) {
                    int j = ox + 3 - 2*qp;
                    if (j >= 0) {
                        g_qsh[(size_t)(qp*2+0)*QSH_PLANE_ELEM + chbase + j] = hh;
                        g_qsh[(size_t)(qp*2+1)*QSH_PLANE_ELEM + chbase + j] = ll;
                    }
                }
            } else {
                g_v[((b*16 + (oc-24))*H2 + oy)*H2 + ox] = val;
            }
        }
    }
}

// ===========================================================================
// Kernel S via mma.sync, cp.async double-buffered, fragment-pipelined.
// 256 threads / 8 warps; warp tile = 32 M-rows x 32 N-cols.
// ===========================================================================
#define SM_AH    0
#define SM_AL    32768
#define SM_BH    65536
#define SM_BL    81920
#define BUFSTRIDE 98304
#define SM_TOT   (2*BUFSTRIDE)    // 192 KB

extern __shared__ char dsm[];

__device__ __forceinline__ void fill_tiles(uint32_t smem, uint32_t bufbase,
        int ky, int tid, const char* qbase, const char* xbase)
{
    #pragma unroll
    for (int k = 0; k < 16; k++) {
        int idx = tid + 256*k;
        int ch = idx & 15, m = (idx >> 4) & 127, mat = idx >> 11;
        int qp = m & 3, p = (m >> 2) & 3, qc = m >> 4;
        int r = ky + 2*p - 3;
        unsigned ok = ((unsigned)r < 112u);
        const char* src = qbase + (qp*2+mat)*QSH_MATSTRIDE + qc*QSH_QCSTRIDE
                        + (ok ? r : 0)*256 + ch*16;
        uint32_t dst = smem + bufbase + (mat ? SM_AL : SM_AH)
                     + m*256 + ((ch ^ (m & 7))*16);
        CP_ASYNC16(dst, src, ok ? 16u : 0u);
    }
    #pragma unroll
    for (int k = 0; k < 8; k++) {
        int idx = tid + 256*k;
        int ch = idx & 15, n = (idx >> 4) & 63, mat = idx >> 10;
        int u = n >> 3, v = n & 7;
        int r = 2*ky - 3 + u;
        unsigned ok = (v < 7) && (u < 7) && ((unsigned)r < 224u);
        const char* src = xbase + ((ok ? v : 0)*2+mat)*XSH_MATSTRIDE
                        + (ok ? r : 0)*256 + ch*16;
        uint32_t dst = smem + bufbase + (mat ? SM_BL : SM_BH)
                     + n*256 + ((ch ^ (n & 7))*16);
        CP_ASYNC16(dst, src, ok ? 16u : 0u);
    }
}

__global__ __launch_bounds__(256) void k_S_mma()
{
    const uint32_t smem = smem_to_u32(dsm);
    const int tid = threadIdx.x, w = tid >> 5, lane = tid & 31;
    const int mslice = w & 3, nhalf = w >> 2;
    const int bx = blockIdx.x;               // 144 = (b,i,c), c fastest
    const int c = bx % 3, i = (bx/3) % 3, b = bx/9;
    const int bi8 = (b*3 + i)*8, bc = b*3 + c;

    const char* qbase = (const char*)g_qsh + (size_t)bi8*QSH_QCSTRIDE;
    const char* xbase = (const char*)g_xsh + (size_t)bc*XSH_BCSTRIDE;

    float acc[2][4][4];                      // [mf][n8][elem]
    #pragma unroll
    for (int mf = 0; mf < 2; mf++)
      #pragma unroll
      for (int n = 0; n < 4; n++)
        #pragma unroll
        for (int e = 0; e < 4; e++) acc[mf][n][e] = 0.f;

    const int rA0 = mslice*32 + (lane & 15);
    const uint32_t aArx = (rA0 & 7)*16;
    const uint32_t aAoff0 = rA0*256, aAoff1 = (rA0+16)*256;
    const int hA = (lane >> 4) & 1;
    const int rBo = (lane & 7) + ((lane & 16) >> 1);
    const uint32_t bBrx = (lane & 7)*16;
    const int hB = (lane >> 3) & 1;

    // fragment double-buffer registers
    uint32_t ah[2][2][4], al[2][2][4], bh[2][2][4], bl[2][2][4];

#define LOAD_FRAG(st, ks_) do { \
    const uint32_t cA = (uint32_t)(2*(ks_) + hA)*16; \
    LDSM_X4(ah[st][0][0],ah[st][0][1],ah[st][0][2],ah[st][0][3], base + SM_AH + aAoff0 + (cA ^ aArx)); \
    LDSM_X4(ah[st][1][0],ah[st][1][1],ah[st][1][2],ah[st][1][3], base + SM_AH + aAoff1 + (cA ^ aArx)); \
    LDSM_X4(al[st][0][0],al[st][0][1],al[st][0][2],al[st][0][3], base + SM_AL + aAoff0 + (cA ^ aArx)); \
    LDSM_X4(al[st][1][0],al[st][1][1],al[st][1][2],al[st][1][3], base + SM_AL + aAoff1 + (cA ^ aArx)); \
    const uint32_t cB = (uint32_t)(2*(ks_) + hB)*16; \
    _Pragma("unroll") \
    for (int nl = 0; nl < 2; nl++) { \
        const int nbp = nhalf*2 + nl; \
        const uint32_t rbB = (uint32_t)(nbp*16 + rBo)*256 + (cB ^ bBrx); \
        LDSM_X4(bh[st][nl][0],bh[st][nl][1],bh[st][nl][2],bh[st][nl][3], base + SM_BH + rbB); \
        LDSM_X4(bl[st][nl][0],bl[st][nl][1],bl[st][nl][2],bl[st][nl][3], base + SM_BL + rbB); \
    } \
} while (0)

    fill_tiles(smem, 0, 0, tid, qbase, xbase);          CP_COMMIT();
    fill_tiles(smem, BUFSTRIDE, 1, tid, qbase, xbase);  CP_COMMIT();

    for (int ky = 0; ky < 112; ky++) {
        if (ky == 111) { CP_WAIT0(); } else { CP_WAIT1(); }
        __syncthreads();                  // buf[ky&1] visible to all warps

        const uint32_t base = smem + (uint32_t)(ky & 1)*BUFSTRIDE;

        LOAD_FRAG(0, 0);
        #pragma unroll
        for (int ks = 0; ks < 7; ks++) {
            const int cur = ks & 1;
            if (ks < 6) LOAD_FRAG(cur ^ 1, ks + 1);
            // pass hh
            #pragma unroll
            for (int mf = 0; mf < 2; mf++)
              #pragma unroll
              for (int nl = 0; nl < 2; nl++) {
                MMA16816(acc[mf][2*nl],   ah[cur][mf], bh[cur][nl][0], bh[cur][nl][1]);
                MMA16816(acc[mf][2*nl+1], ah[cur][mf], bh[cur][nl][2], bh[cur][nl][3]);
              }
            // pass hl
            #pragma unroll
            for (int mf = 0; mf < 2; mf++)
              #pragma unroll
              for (int nl = 0; nl < 2; nl++) {
                MMA16816(acc[mf][2*nl],   ah[cur][mf], bl[cur][nl][0], bl[cur][nl][1]);
                MMA16816(acc[mf][2*nl+1], ah[cur][mf], bl[cur][nl][2], bl[cur][nl][3]);
              }
            // pass lh
            #pragma unroll
            for (int mf = 0; mf < 2; mf++)
              #pragma unroll
              for (int nl = 0; nl < 2; nl++) {
                MMA16816(acc[mf][2*nl],   al[cur][mf], bh[cur][nl][0], bh[cur][nl][1]);
                MMA16816(acc[mf][2*nl+1], al[cur][mf], bh[cur][nl][2], bh[cur][nl][3]);
              }
        }
        __syncthreads();                  // all reads of buf[ky&1] done
        if (ky + 2 < 112) {
            fill_tiles(smem, (uint32_t)(ky & 1)*BUFSTRIDE, ky + 2, tid, qbase, xbase);
            CP_COMMIT();
        }
    }
#undef LOAD_FRAG

    // ---- epilogue: scatter live fragments to g_S (dead: nb==7 / vv==7)
    #pragma unroll
    for (int mf = 0; mf < 2; mf++) {
        #pragma unroll
        for (int j = 0; j < 4; j++) {
            const int nb = nhalf*4 + j;
            if (nb == 7) continue;
            const int ncol = nb*8 + 2*(lane & 3);
            #pragma unroll
            for (int hf = 0; hf < 2; hf++) {
                int m = mslice*32 + mf*16 + (lane >> 2) + hf*8;
                int qc = m >> 4, pq = m & 15;
                float* So = g_S + ((((b*3+i)*8 + qc)*3 + c)*784 + pq*49);
                #pragma unroll
                for (int e = 0; e < 2; e++) {
                    int n = ncol + e;
                    int vv = n & 7;
                    if (vv < 7) So[nb*7 + vv] = acc[mf][j][hf*2 + e];
                }
            }
        }
    }
}

// ===========================================================================
// Kernel Qs: clipped window sums of q, MLP-4. grid 384 = (b,i,qc)
// ===========================================================================
__global__ __launch_bounds__(128) void k_qs()
{
    __shared__ float cs[4][114];
    const int bx = blockIdx.x;
    const float* Q = g_q + bx*H2*H2;
    const int tid = threadIdx.x;
    if (tid < 112) {
        float a0=0.f, a1=0.f, a2=0.f, a3=0.f;
        for (int y = 0; y < 112; y += 4) {
            a0 += Q[(y  )*H2 + tid];
            a1 += Q[(y+1)*H2 + tid];
            a2 += Q[(y+2)*H2 + tid];
            a3 += Q[(y+3)*H2 + tid];
        }
        float full = (a0+a1)+(a2+a3);
        float e0   = Q[tid],          e1   = Q[H2 + tid],     e2   = Q[2*H2 + tid];
        float e109 = Q[109*H2 + tid], e110 = Q[110*H2 + tid], e111 = Q[111*H2 + tid];
        cs[0][tid] = full - e109 - e110 - e111;
        cs[1][tid] = full - e111;
        cs[2][tid] = full - e0;
        cs[3][tid] = full - e0 - e1 - e2;
    }
    __syncthreads();
    if (tid < 16) {
        int p = tid >> 2, qx = tid & 3;
        int xs_ = (qx <= 1) ? 0 : (qx == 2 ? 1 : 3);
        int xe_ = (qx == 0) ? 109 : (qx == 1 ? 111 : 112);
        float s = 0.f;
        for (int xc = xs_; xc < xe_; xc++) s += cs[p][xc];
        g_Qs[bx*16 + tid] = s;
    }
}

// ===========================================================================
// Kernel a: grid 768 = (b,i,vc); 256 thr = 16 K-slices x 16 pq
// ===========================================================================
__global__ __launch_bounds__(256) void k_a(const float* __restrict__ Wk,
                                           const float* __restrict__ bk)
{
    const int bx = blockIdx.x;
    const int vc = bx & 15, bi = bx >> 4;
    const int i = bi % 3;
    const int tid = threadIdx.x;
    const int s = tid & 15, pq = tid >> 4;
    const float* Sb = g_S + bi*24*784;
    const float* Wb = Wk + i*(VCn*QCn*ICn*49) + vc*(QCn*ICn*49);
    float acc = 0.f;
    #pragma unroll 1
    for (int qcc = 0; qcc < 24; qcc++) {
        const float* Sp = Sb + qcc*784 + pq*49;
        const float* Wp = Wb + qcc*49;
        #pragma unroll
        for (int uv = s; uv < 49; uv += 16) acc += Wp[uv]*Sp[uv];
    }
    #pragma unroll
    for (int o = 8; o; o >>= 1) acc += __shfl_down_sync(0xffffffffu, acc, o, 16);
    if (s == 0) {
        const float* Qsb = g_Qs + bi*8*16;
        float bterm = 0.f;
        #pragma unroll
        for (int qc = 0; qc < 8; qc++)
            bterm += bk[(i*16+vc)*8+qc] * Qsb[qc*16+pq];
        g_a[bi*256 + vc*16 + pq] = acc + bterm;
    }
}

// ===========================================================================
// Kernel o: o[b,i,58,58] = dynconv(v[b], a[b,i]); grid (48, 14)
// ===========================================================================
__global__ __launch_bounds__(256) void k_o(float* __restrict__ out)
{
    __shared__ float as_[256];
    const int bx = blockIdx.x;
    const int b = bx/3;
    const int tid = threadIdx.x;
    as_[tid] = g_a[bx*256 + tid];
    __syncthreads();

    const int idx = blockIdx.y*256 + tid;
    if (idx >= 58*58) return;
    const int oy = idx/58, ox = idx%58;
    const float* vb = g_v + b*16*H2*H2;
    float acc = 0.f;
    for (int vc = 0; vc < 16; vc++) {
        const float* vp = vb + vc*H2*H2;
        const float* ap = &as_[vc*16];
        #pragma unroll
        for (int ky = 0; ky < 4; ky++) {
            int r = 2*oy - 3 + ky;
            if (r < 0 || r >= H2) continue;
            #pragma unroll
            for (int kx = 0; kx < 4; kx++) {
                int cc = 2*ox - 3 + kx;
                if (cc < 0 || cc >= H2) continue;
                acc += ap[ky*4+kx] * vp[r*H2 + cc];
            }
        }
    }
    out[bx*3364 + idx] = acc;
}

extern "C" void kernel_launch(void* const* d_in, const int* in_sizes, int n_in,
                              void* d_out, int out_size)
{
    const float* x  = (const float*)d_in[0];
    const float* Wq = (const float*)d_in[1];
    const float* bq = (const float*)d_in[2];
    const float* Wk = (const float*)d_in[3];
    const float* bk = (const float*)d_in[4];
    const float* Wv = (const float*)d_in[5];
    const float* bv = (const float*)d_in[6];
    float* out = (float*)d_out;

    cudaFuncSetAttribute(k_S_mma, cudaFuncAttributeMaxDynamicSharedMemorySize, SM_TOT);

    k_convqv<<<dim3(112,16), 224>>>(x, Wq, bq, Wv, bv);
    k_S_mma <<<144, 256, SM_TOT>>>();
    k_qs    <<<384, 128>>>();
    k_a     <<<768, 256>>>(Wk, bk);
    k_o     <<<dim3(48,14), 256>>>(out);
}